// round 8
// baseline (speedup 1.0000x reference)
#include <cuda_runtime.h>
#include <cstdint>
#include <math.h>

#define HH 256
#define WW 256
#define NPIX 65536
#define CCH 32

// block roles: [0,296) RNG producers, [296,444) D producers, [444,956) matchers
#define NRNGB 296
#define NDB   148
#define NMB   512
#define NGRID (NRNGB + NDB + NMB)
#define RNGT  (NRNGB * 256)          // 75776 RNG threads

// ---------------- scratch / flags ----------------
__device__ float g_D[2 * NPIX];              // reference-ordered patch SSD table
__device__ float g_N[20 * 4 * NPIX];         // normals: [(it*4+s)][bch][p]
__device__ uint32_t g_flagD;
__device__ uint32_t g_flagN[5];
__device__ uint32_t g_fin;

struct AllKeys { uint32_t k[5][4][2]; };

// ---------------- threefry-2x32 ----------------
__host__ __device__ __forceinline__ uint32_t rotl32(uint32_t v, int d) {
    return (v << d) | (v >> (32 - d));
}

__host__ __device__ __forceinline__ void threefry(uint32_t k0, uint32_t k1,
                                                  uint32_t x0, uint32_t x1,
                                                  uint32_t& o0, uint32_t& o1) {
    uint32_t k2 = k0 ^ k1 ^ 0x1BD11BDAu;
    x0 += k0; x1 += k1;
    x0 += x1; x1 = rotl32(x1, 13); x1 ^= x0;
    x0 += x1; x1 = rotl32(x1, 15); x1 ^= x0;
    x0 += x1; x1 = rotl32(x1, 26); x1 ^= x0;
    x0 += x1; x1 = rotl32(x1, 6);  x1 ^= x0;
    x0 += k1; x1 += k2 + 1u;
    x0 += x1; x1 = rotl32(x1, 17); x1 ^= x0;
    x0 += x1; x1 = rotl32(x1, 29); x1 ^= x0;
    x0 += x1; x1 = rotl32(x1, 16); x1 ^= x0;
    x0 += x1; x1 = rotl32(x1, 24); x1 ^= x0;
    x0 += k2; x1 += k0 + 2u;
    x0 += x1; x1 = rotl32(x1, 13); x1 ^= x0;
    x0 += x1; x1 = rotl32(x1, 15); x1 ^= x0;
    x0 += x1; x1 = rotl32(x1, 26); x1 ^= x0;
    x0 += x1; x1 = rotl32(x1, 6);  x1 ^= x0;
    x0 += k0; x1 += k1 + 3u;
    x0 += x1; x1 = rotl32(x1, 17); x1 ^= x0;
    x0 += x1; x1 = rotl32(x1, 29); x1 ^= x0;
    x0 += x1; x1 = rotl32(x1, 16); x1 ^= x0;
    x0 += x1; x1 = rotl32(x1, 24); x1 ^= x0;
    x0 += k1; x1 += k2 + 4u;
    x0 += x1; x1 = rotl32(x1, 13); x1 ^= x0;
    x0 += x1; x1 = rotl32(x1, 15); x1 ^= x0;
    x0 += x1; x1 = rotl32(x1, 26); x1 ^= x0;
    x0 += x1; x1 = rotl32(x1, 6);  x1 ^= x0;
    x0 += k2; x1 += k0 + 5u;
    o0 = x0; o1 = x1;
}

__device__ __forceinline__ uint32_t rnd32(uint32_t k0, uint32_t k1, uint32_t i) {
    uint32_t o0, o1;
    threefry(k0, k1, 0u, i, o0, o1);
    return o0 ^ o1;
}

// ---------------- float helpers (XLA-matching: NO fma contraction) ----------------
__device__ __forceinline__ float bits_to_f01(uint32_t v) {
    return __fadd_rn(__uint_as_float((v >> 9) | 0x3F800000u), -1.0f);
}

__device__ __forceinline__ float erfinv_xla(float x) {
    float t = __fmul_rn(x, x);
    float w = -log1pf(-t);
    float p;
    if (w < 5.0f) {
        w = __fadd_rn(w, -2.5f);
        p = 2.81022636e-08f;
        p = __fadd_rn(3.43273939e-07f,  __fmul_rn(p, w));
        p = __fadd_rn(-3.5233877e-06f,  __fmul_rn(p, w));
        p = __fadd_rn(-4.39150654e-06f, __fmul_rn(p, w));
        p = __fadd_rn(0.00021858087f,   __fmul_rn(p, w));
        p = __fadd_rn(-0.00125372503f,  __fmul_rn(p, w));
        p = __fadd_rn(-0.00417768164f,  __fmul_rn(p, w));
        p = __fadd_rn(0.246640727f,     __fmul_rn(p, w));
        p = __fadd_rn(1.50140941f,      __fmul_rn(p, w));
    } else {
        w = __fadd_rn(__fsqrt_rn(w), -3.0f);
        p = -0.000200214257f;
        p = __fadd_rn(0.000100950558f,  __fmul_rn(p, w));
        p = __fadd_rn(0.00134934322f,   __fmul_rn(p, w));
        p = __fadd_rn(-0.00367342844f,  __fmul_rn(p, w));
        p = __fadd_rn(0.00573950773f,   __fmul_rn(p, w));
        p = __fadd_rn(-0.0076224613f,   __fmul_rn(p, w));
        p = __fadd_rn(0.00943887047f,   __fmul_rn(p, w));
        p = __fadd_rn(1.00167406f,      __fmul_rn(p, w));
        p = __fadd_rn(2.83297682f,      __fmul_rn(p, w));
    }
    return __fmul_rn(p, x);
}

__device__ __forceinline__ float normal_from_bits(uint32_t v) {
    float f = bits_to_f01(v);
    float u = __fadd_rn(__fmul_rn(f, 2.0f), -0.99999994f);
    u = fmaxf(-0.99999994f, u);
    return __fmul_rn(1.4142135623730951f, erfinv_xla(u));
}

// COHERENT lookup (ld.global.cg): g_D is produced by this same grid.
__device__ __forceinline__ float dlookup(int b, float y, float x) {
    int iy = __float2int_rn(y);
    int ix = __float2int_rn(x);
    iy = min(max(iy, 0), HH - 1);
    ix = min(max(ix, 0), WW - 1);
    return __ldcg(&g_D[b * NPIX + iy * WW + ix]);
}

__device__ __forceinline__ void spin_until(uint32_t* flag, uint32_t target) {
    uint32_t v;
    do {
        asm volatile("ld.acquire.gpu.u32 %0, [%1];"
                     : "=r"(v) : "l"(flag) : "memory");
        if (v < target) __nanosleep(128);
    } while (v < target);
}

// ---------------- mega kernel ----------------
#define TSX 32
#define TSY 8
#define HX 34
#define HSLOTS (HX * 10)   // 340

__global__ __launch_bounds__(256, 5) void kMega(const float* __restrict__ src,
                                                const float* __restrict__ tgt,
                                                float* __restrict__ out,
                                                uint32_t ka, uint32_t kb,
                                                AllKeys keys) {
    __shared__ float sq[CCH * HSLOTS];   // 43520 B; matchers reuse the front
    int tid = threadIdx.x;
    int bi  = blockIdx.x;

    if (bi < NRNGB) {
        // ======== RNG producer: persistent, iteration-major ========
        uint32_t rtid = (uint32_t)(bi * 256 + tid);   // 0..75775
        for (int it = 0; it < 5; it++) {
#pragma unroll
            for (int k = 0; k < 4; k++) {
                uint32_t g = rtid + (uint32_t)(k * RNGT);
                if (k < 3 || g < 262144u) {
#pragma unroll
                    for (int s = 0; s < 4; s++) {
                        float n = normal_from_bits(
                            rnd32(keys.k[it][s][0], keys.k[it][s][1], g));
                        g_N[(uint32_t)(it * 4 + s) * 262144u + g] = n;
                    }
                }
            }
            __threadfence();
            __syncthreads();
            if (tid == 0) atomicAdd(&g_flagN[it], 1u);
        }
    } else if (bi < NRNGB + NDB) {
        // ======== D producer: persistent over tiles ========
        for (int tIdx = bi - NRNGB; tIdx < 512; tIdx += NDB) {
            int tileX = tIdx & 7;
            int tileY = (tIdx >> 3) & 31;
            int b     = tIdx >> 8;
            int baseY = tileY * TSY - 1;
            int baseX = tileX * TSX - 1;

            {
                int j = tid;
                int yh = j / HX, xh = j % HX;
                int gy = baseY + yh, gx = baseX + xh;
                bool inb = ((unsigned)gy < HH) && ((unsigned)gx < WW);
                int gidx = (b * CCH) * NPIX + gy * WW + gx;
#pragma unroll
                for (int c = 0; c < CCH; c++) {
                    float v = 0.0f;
                    if (inb) {
                        float d = __fsub_rn(__ldg(&src[gidx + c * NPIX]),
                                            __ldg(&tgt[gidx + c * NPIX]));
                        v = __fmul_rn(d, d);
                    }
                    sq[c * HSLOTS + j] = v;
                }
                int j2 = tid + 256;
                if (j2 < HSLOTS) {
                    int yh2 = j2 / HX, xh2 = j2 % HX;
                    int gy2 = baseY + yh2, gx2 = baseX + xh2;
                    bool inb2 = ((unsigned)gy2 < HH) && ((unsigned)gx2 < WW);
                    int gidx2 = (b * CCH) * NPIX + gy2 * WW + gx2;
#pragma unroll
                    for (int c = 0; c < CCH; c++) {
                        float v = 0.0f;
                        if (inb2) {
                            float d = __fsub_rn(__ldg(&src[gidx2 + c * NPIX]),
                                                __ldg(&tgt[gidx2 + c * NPIX]));
                            v = __fmul_rn(d, d);
                        }
                        sq[c * HSLOTS + j2] = v;
                    }
                }
            }
            __syncthreads();

            int tx = tid & 31, ty = tid >> 5;
            float acc = 0.0f;
#pragma unroll
            for (int dy = 0; dy < 3; dy++) {
#pragma unroll
                for (int dx = 0; dx < 3; dx++) {
                    const float* pb = &sq[(ty + dy) * HX + (tx + dx)];
#pragma unroll
                    for (int c = 0; c < CCH; c++) {
                        acc = __fadd_rn(acc, pb[c * HSLOTS]);
                    }
                }
            }
            g_D[b * NPIX + (tileY * TSY + ty) * WW + (tileX * TSX + tx)] = acc;
            __syncthreads();   // smem reuse barrier before next tile fill
        }
        __threadfence();
        __syncthreads();
        if (tid == 0) atomicAdd(&g_flagD, 1u);
    } else {
        // ======== matcher: init + 5 PatchMatch iterations (one row) ========
        float* sy = sq;
        float* sx = sq + 256;
        float* sd = sq + 512;
        int bid2 = bi - (NRNGB + NDB);
        int b   = bid2 >> 8;
        int row = bid2 & 255;
        int t   = tid;
        int p   = (row << 8) | t;

        uint32_t ciy = (uint32_t)(b * 131072 + p);
        uint32_t cix = ciy + 65536u;

        // pure-ALU init draws overlap the D-spin
        float y = __fmul_rn(bits_to_f01(rnd32(ka, kb, ciy)), 255.0f);
        float x = __fmul_rn(bits_to_f01(rnd32(ka, kb, cix)), 255.0f);

        if (t == 0) spin_until(&g_flagD, NDB);
        __syncthreads();
        float d = dlookup(b, y, x);

        int tm = (t + 255) & 255;
        int tp = (t + 1) & 255;
        const float scales[4] = {1.0f, 0.5f, 0.25f, 0.125f};

#pragma unroll
        for (int it = 0; it < 5; it++) {
            sy[t] = y; sx[t] = x; sd[t] = d;
            if (t == 0) spin_until(&g_flagN[it], NRNGB);
            __syncthreads();

            // coherent (.cg) reads: g_N written by this grid
            float nrm[8];
#pragma unroll
            for (int s = 0; s < 4; s++) {
                uint32_t base = (uint32_t)(it * 4 + s) * 262144u;
                nrm[2 * s]     = __ldcg(&g_N[base + ciy]);
                nrm[2 * s + 1] = __ldcg(&g_N[base + cix]);
            }
            float my = sy[tm], mx = sx[tm], md = sd[tm];
            float qy = sy[tp], qx = sx[tp], qd = sd[tp];
            __syncthreads();

            // propagate(+1) at p and p+1, then propagate(-1) at p
            float c0y, c0x, c0d, c1y, c1x, c1d;
            if (md < d) { c0y = my; c0x = mx; c0d = md; } else { c0y = y; c0x = x; c0d = d; }
            if (d < qd) { c1y = y;  c1x = x;  c1d = d;  } else { c1y = qy; c1x = qx; c1d = qd; }
            if (c1d < c0d) { y = c1y; x = c1x; d = c1d; } else { y = c0y; x = c0x; d = c0d; }

            // 4-step random search
#pragma unroll
            for (int s = 0; s < 4; s++) {
                float ry = __fadd_rn(y, __fmul_rn(nrm[2 * s], scales[s]));
                float rx = __fadd_rn(x, __fmul_rn(nrm[2 * s + 1], scales[s]));
                ry = fminf(fmaxf(ry, 0.0f), 255.0f);
                rx = fminf(fmaxf(rx, 0.0f), 255.0f);
                float rd = dlookup(b, ry, rx);
                if (rd < d) { y = ry; x = rx; d = rd; }
            }
        }

        out[b * 131072 + p]        = y;
        out[b * 131072 + NPIX + p] = x;

        // last matcher resets all flags for the next (deterministic) replay
        __threadfence();
        __syncthreads();
        if (t == 0) {
            uint32_t v = atomicAdd(&g_fin, 1u);
            if (v == NMB - 1) {
                *(volatile uint32_t*)&g_flagD = 0u;
#pragma unroll
                for (int i = 0; i < 5; i++) *(volatile uint32_t*)&g_flagN[i] = 0u;
                *(volatile uint32_t*)&g_fin = 0u;
                __threadfence();
            }
        }
    }
}

// ---------------- host ----------------
extern "C" void kernel_launch(void* const* d_in, const int* in_sizes, int n_in,
                              void* d_out, int out_size) {
    const float* src = (const float*)d_in[0];
    const float* tgt = (const float*)d_in[1];
    float* out = (float*)d_out;
    (void)in_sizes; (void)n_in; (void)out_size;

    uint32_t ki0, ki1, kl0, kl1;
    threefry(0u, 1u, 0u, 0u, ki0, ki1);   // k_init
    threefry(0u, 1u, 0u, 1u, kl0, kl1);   // k_loop

    AllKeys keys;
    for (uint32_t t = 0; t < 5; t++) {
        uint32_t K0, K1;
        threefry(kl0, kl1, 0u, t, K0, K1);        // fold_in(k_loop, t)
        for (int s = 0; s < 4; s++) {
            uint32_t n0, n1, s0, s1;
            threefry(K0, K1, 0u, 0u, n0, n1);     // next key
            threefry(K0, K1, 0u, 1u, s0, s1);     // key for normal draw
            keys.k[t][s][0] = s0;
            keys.k[t][s][1] = s1;
            K0 = n0; K1 = n1;
        }
    }

    kMega<<<NGRID, 256>>>(src, tgt, out, ki0, ki1, keys);
}

// round 9
// speedup vs baseline: 1.3387x; 1.3387x over previous
#include <cuda_runtime.h>
#include <cstdint>
#include <math.h>

#define HH 256
#define WW 256
#define NPIX 65536
#define CCH 32

// ---------------- scratch ----------------
__device__ float g_D[2 * NPIX];              // reference-ordered patch SSD table
__device__ float g_N[20 * 4 * NPIX];         // normals: [(it*4+s)][bch][p]

struct AllKeys { uint32_t k[5][4][2]; };

// ---------------- threefry-2x32 ----------------
__host__ __device__ __forceinline__ uint32_t rotl32(uint32_t v, int d) {
    return (v << d) | (v >> (32 - d));
}

__host__ __device__ __forceinline__ void threefry(uint32_t k0, uint32_t k1,
                                                  uint32_t x0, uint32_t x1,
                                                  uint32_t& o0, uint32_t& o1) {
    uint32_t k2 = k0 ^ k1 ^ 0x1BD11BDAu;
    x0 += k0; x1 += k1;
    x0 += x1; x1 = rotl32(x1, 13); x1 ^= x0;
    x0 += x1; x1 = rotl32(x1, 15); x1 ^= x0;
    x0 += x1; x1 = rotl32(x1, 26); x1 ^= x0;
    x0 += x1; x1 = rotl32(x1, 6);  x1 ^= x0;
    x0 += k1; x1 += k2 + 1u;
    x0 += x1; x1 = rotl32(x1, 17); x1 ^= x0;
    x0 += x1; x1 = rotl32(x1, 29); x1 ^= x0;
    x0 += x1; x1 = rotl32(x1, 16); x1 ^= x0;
    x0 += x1; x1 = rotl32(x1, 24); x1 ^= x0;
    x0 += k2; x1 += k0 + 2u;
    x0 += x1; x1 = rotl32(x1, 13); x1 ^= x0;
    x0 += x1; x1 = rotl32(x1, 15); x1 ^= x0;
    x0 += x1; x1 = rotl32(x1, 26); x1 ^= x0;
    x0 += x1; x1 = rotl32(x1, 6);  x1 ^= x0;
    x0 += k0; x1 += k1 + 3u;
    x0 += x1; x1 = rotl32(x1, 17); x1 ^= x0;
    x0 += x1; x1 = rotl32(x1, 29); x1 ^= x0;
    x0 += x1; x1 = rotl32(x1, 16); x1 ^= x0;
    x0 += x1; x1 = rotl32(x1, 24); x1 ^= x0;
    x0 += k1; x1 += k2 + 4u;
    x0 += x1; x1 = rotl32(x1, 13); x1 ^= x0;
    x0 += x1; x1 = rotl32(x1, 15); x1 ^= x0;
    x0 += x1; x1 = rotl32(x1, 26); x1 ^= x0;
    x0 += x1; x1 = rotl32(x1, 6);  x1 ^= x0;
    x0 += k2; x1 += k0 + 5u;
    o0 = x0; o1 = x1;
}

__device__ __forceinline__ uint32_t rnd32(uint32_t k0, uint32_t k1, uint32_t i) {
    uint32_t o0, o1;
    threefry(k0, k1, 0u, i, o0, o1);
    return o0 ^ o1;
}

// ---------------- float helpers (XLA-matching: NO fma contraction) ----------------
__device__ __forceinline__ float bits_to_f01(uint32_t v) {
    return __fadd_rn(__uint_as_float((v >> 9) | 0x3F800000u), -1.0f);
}

__device__ __forceinline__ float erfinv_xla(float x) {
    float t = __fmul_rn(x, x);
    float w = -log1pf(-t);
    float p;
    if (w < 5.0f) {
        w = __fadd_rn(w, -2.5f);
        p = 2.81022636e-08f;
        p = __fadd_rn(3.43273939e-07f,  __fmul_rn(p, w));
        p = __fadd_rn(-3.5233877e-06f,  __fmul_rn(p, w));
        p = __fadd_rn(-4.39150654e-06f, __fmul_rn(p, w));
        p = __fadd_rn(0.00021858087f,   __fmul_rn(p, w));
        p = __fadd_rn(-0.00125372503f,  __fmul_rn(p, w));
        p = __fadd_rn(-0.00417768164f,  __fmul_rn(p, w));
        p = __fadd_rn(0.246640727f,     __fmul_rn(p, w));
        p = __fadd_rn(1.50140941f,      __fmul_rn(p, w));
    } else {
        w = __fadd_rn(__fsqrt_rn(w), -3.0f);
        p = -0.000200214257f;
        p = __fadd_rn(0.000100950558f,  __fmul_rn(p, w));
        p = __fadd_rn(0.00134934322f,   __fmul_rn(p, w));
        p = __fadd_rn(-0.00367342844f,  __fmul_rn(p, w));
        p = __fadd_rn(0.00573950773f,   __fmul_rn(p, w));
        p = __fadd_rn(-0.0076224613f,   __fmul_rn(p, w));
        p = __fadd_rn(0.00943887047f,   __fmul_rn(p, w));
        p = __fadd_rn(1.00167406f,      __fmul_rn(p, w));
        p = __fadd_rn(2.83297682f,      __fmul_rn(p, w));
    }
    return __fmul_rn(p, x);
}

__device__ __forceinline__ float normal_from_bits(uint32_t v) {
    float f = bits_to_f01(v);
    float u = __fadd_rn(__fmul_rn(f, 2.0f), -0.99999994f);
    u = fmaxf(-0.99999994f, u);
    return __fmul_rn(1.4142135623730951f, erfinv_xla(u));
}

__device__ __forceinline__ float clipc(float v) {
    return fminf(fmaxf(v, 0.0f), 255.0f);
}

__device__ __forceinline__ int daddr(int b, float y, float x) {
    int iy = __float2int_rn(y);
    int ix = __float2int_rn(x);
    iy = min(max(iy, 0), HH - 1);
    ix = min(max(ix, 0), WW - 1);
    return b * NPIX + iy * WW + ix;
}

// ---------------- kernel 1: heterogeneous prep (RNG blocks FIRST) ----------------
// blocks [0, 1024):    normal table fill (20 threefry+erfinv per thread)
// blocks [1024, 1536): fused SQ + strict-order D via smem halo tiles
#define TSX 32
#define TSY 8
#define HX 34
#define HSLOTS (HX * 10)   // 340

__global__ __launch_bounds__(256, 4) void kPrep(const float* __restrict__ src,
                                                const float* __restrict__ tgt,
                                                AllKeys keys) {
    __shared__ float sq[CCH * HSLOTS];   // 43520 B (reserved for all blocks)
    int tid = threadIdx.x;
    int bi  = blockIdx.x;

    if (bi >= 1024) {
        // ---- SQ + D tile ----
        int tb = bi - 1024;
        int tileX = tb & 7;
        int tileY = (tb >> 3) & 31;
        int b     = tb >> 8;
        int baseY = tileY * TSY - 1;
        int baseX = tileX * TSX - 1;

        {
            int j = tid;
            int yh = j / HX, xh = j % HX;
            int gy = baseY + yh, gx = baseX + xh;
            bool inb = ((unsigned)gy < HH) && ((unsigned)gx < WW);
            int gidx = (b * CCH) * NPIX + gy * WW + gx;
#pragma unroll
            for (int c = 0; c < CCH; c++) {
                float v = 0.0f;
                if (inb) {
                    float d = __fsub_rn(__ldg(&src[gidx + c * NPIX]),
                                        __ldg(&tgt[gidx + c * NPIX]));
                    v = __fmul_rn(d, d);
                }
                sq[c * HSLOTS + j] = v;
            }
            int j2 = tid + 256;
            if (j2 < HSLOTS) {
                int yh2 = j2 / HX, xh2 = j2 % HX;
                int gy2 = baseY + yh2, gx2 = baseX + xh2;
                bool inb2 = ((unsigned)gy2 < HH) && ((unsigned)gx2 < WW);
                int gidx2 = (b * CCH) * NPIX + gy2 * WW + gx2;
#pragma unroll
                for (int c = 0; c < CCH; c++) {
                    float v = 0.0f;
                    if (inb2) {
                        float d = __fsub_rn(__ldg(&src[gidx2 + c * NPIX]),
                                            __ldg(&tgt[gidx2 + c * NPIX]));
                        v = __fmul_rn(d, d);
                    }
                    sq[c * HSLOTS + j2] = v;
                }
            }
        }
        __syncthreads();

        int tx = tid & 31, ty = tid >> 5;
        float acc = 0.0f;
#pragma unroll
        for (int dy = 0; dy < 3; dy++) {
#pragma unroll
            for (int dx = 0; dx < 3; dx++) {
                const float* pb = &sq[(ty + dy) * HX + (tx + dx)];
#pragma unroll
                for (int c = 0; c < CCH; c++) {
                    acc = __fadd_rn(acc, pb[c * HSLOTS]);
                }
            }
        }
        g_D[b * NPIX + (tileY * TSY + ty) * WW + (tileX * TSX + tx)] = acc;
    } else {
        // ---- normal table: thread <-> (bch, p), counter = gtid ----
        uint32_t gtid = (uint32_t)(bi * 256 + tid);   // 0..262143
        for (int it = 0; it < 5; it++) {
#pragma unroll
            for (int s = 0; s < 4; s++) {
                float n = normal_from_bits(
                    rnd32(keys.k[it][s][0], keys.k[it][s][1], gtid));
                g_N[(uint32_t)(it * 4 + s) * 262144u + gtid] = n;
            }
        }
    }
}

// ---------------- kernel 2: init + 5 PatchMatch iterations ----------------
// 2-level speculative random search: steps (0,1) and (2,3) each resolved from
// one parallel 3-load wall. Selection semantics identical to sequential.
__global__ __launch_bounds__(256) void kMatch(float* __restrict__ out,
                                              uint32_t ka, uint32_t kb) {
    __shared__ float sy[2][256], sx[2][256], sd[2][256];
    int b   = blockIdx.x >> 8;
    int row = blockIdx.x & 255;
    int t   = threadIdx.x;
    int p   = (row << 8) | t;

    uint32_t ciy = (uint32_t)(b * 131072 + p);
    uint32_t cix = ciy + 65536u;

    float y = __fmul_rn(bits_to_f01(rnd32(ka, kb, ciy)), 255.0f);
    float x = __fmul_rn(bits_to_f01(rnd32(ka, kb, cix)), 255.0f);
    float d = __ldg(&g_D[daddr(b, y, x)]);

    int tm = (t + 255) & 255;
    int tp = (t + 1) & 255;

#pragma unroll
    for (int it = 0; it < 5; it++) {
        int cb = it & 1;
        sy[cb][t] = y; sx[cb][t] = x; sd[cb][t] = d;

        // 8 precomputed normals (independent, coalesced)
        float nrm[8];
#pragma unroll
        for (int s = 0; s < 4; s++) {
            uint32_t base = (uint32_t)(it * 4 + s) * 262144u;
            nrm[2 * s]     = __ldg(&g_N[base + ciy]);
            nrm[2 * s + 1] = __ldg(&g_N[base + cix]);
        }

        __syncthreads();
        float my = sy[cb][tm], mx = sx[cb][tm], md = sd[cb][tm];
        float qy = sy[cb][tp], qx = sx[cb][tp], qd = sd[cb][tp];
        // no second sync: next iteration writes the other buffer, and the
        // following reuse of this buffer is fenced by the next sync.

        // propagate(+1) at p and p+1, then propagate(-1) at p
        float c0y, c0x, c0d, c1y, c1x, c1d;
        if (md < d) { c0y = my; c0x = mx; c0d = md; } else { c0y = y; c0x = x; c0d = d; }
        if (d < qd) { c1y = y;  c1x = x;  c1d = d;  } else { c1y = qy; c1x = qx; c1d = qd; }
        if (c1d < c0d) { y = c1y; x = c1x; d = c1d; } else { y = c0y; x = c0x; d = c0d; }

        // ---- speculative pair (steps 0,1): scales 1.0, 0.5 ----
        {
            float a1y = clipc(__fadd_rn(y, __fmul_rn(nrm[0], 1.0f)));
            float a1x = clipc(__fadd_rn(x, __fmul_rn(nrm[1], 1.0f)));
            float r0y = clipc(__fadd_rn(y,   __fmul_rn(nrm[2], 0.5f)));
            float r0x = clipc(__fadd_rn(x,   __fmul_rn(nrm[3], 0.5f)));
            float r1y = clipc(__fadd_rn(a1y, __fmul_rn(nrm[2], 0.5f)));
            float r1x = clipc(__fadd_rn(a1x, __fmul_rn(nrm[3], 0.5f)));
            float d1  = __ldg(&g_D[daddr(b, a1y, a1x)]);
            float d20 = __ldg(&g_D[daddr(b, r0y, r0x)]);
            float d21 = __ldg(&g_D[daddr(b, r1y, r1x)]);
            bool acc1 = d1 < d;
            if (acc1) { y = a1y; x = a1x; d = d1; }
            float dv = acc1 ? d21 : d20;
            float cy = acc1 ? r1y : r0y;
            float cx = acc1 ? r1x : r0x;
            if (dv < d) { y = cy; x = cx; d = dv; }
        }
        // ---- speculative pair (steps 2,3): scales 0.25, 0.125 ----
        {
            float a1y = clipc(__fadd_rn(y, __fmul_rn(nrm[4], 0.25f)));
            float a1x = clipc(__fadd_rn(x, __fmul_rn(nrm[5], 0.25f)));
            float r0y = clipc(__fadd_rn(y,   __fmul_rn(nrm[6], 0.125f)));
            float r0x = clipc(__fadd_rn(x,   __fmul_rn(nrm[7], 0.125f)));
            float r1y = clipc(__fadd_rn(a1y, __fmul_rn(nrm[6], 0.125f)));
            float r1x = clipc(__fadd_rn(a1x, __fmul_rn(nrm[7], 0.125f)));
            float d1  = __ldg(&g_D[daddr(b, a1y, a1x)]);
            float d20 = __ldg(&g_D[daddr(b, r0y, r0x)]);
            float d21 = __ldg(&g_D[daddr(b, r1y, r1x)]);
            bool acc1 = d1 < d;
            if (acc1) { y = a1y; x = a1x; d = d1; }
            float dv = acc1 ? d21 : d20;
            float cy = acc1 ? r1y : r0y;
            float cx = acc1 ? r1x : r0x;
            if (dv < d) { y = cy; x = cx; d = dv; }
        }
    }

    out[b * 131072 + p]        = y;
    out[b * 131072 + NPIX + p] = x;
}

// ---------------- host ----------------
extern "C" void kernel_launch(void* const* d_in, const int* in_sizes, int n_in,
                              void* d_out, int out_size) {
    const float* src = (const float*)d_in[0];
    const float* tgt = (const float*)d_in[1];
    float* out = (float*)d_out;
    (void)in_sizes; (void)n_in; (void)out_size;

    uint32_t ki0, ki1, kl0, kl1;
    threefry(0u, 1u, 0u, 0u, ki0, ki1);   // k_init
    threefry(0u, 1u, 0u, 1u, kl0, kl1);   // k_loop

    AllKeys keys;
    for (uint32_t t = 0; t < 5; t++) {
        uint32_t K0, K1;
        threefry(kl0, kl1, 0u, t, K0, K1);        // fold_in(k_loop, t)
        for (int s = 0; s < 4; s++) {
            uint32_t n0, n1, s0, s1;
            threefry(K0, K1, 0u, 0u, n0, n1);     // next key
            threefry(K0, K1, 0u, 1u, s0, s1);     // key for normal draw
            keys.k[t][s][0] = s0;
            keys.k[t][s][1] = s1;
            K0 = n0; K1 = n1;
        }
    }

    kPrep<<<1536, 256>>>(src, tgt, keys);
    kMatch<<<512, 256>>>(out, ki0, ki1);
}